// round 16
// baseline (speedup 1.0000x reference)
#include <cuda_runtime.h>
#include <stdint.h>
#include <math.h>

constexpr int cS = 512, cB = 64, cE = 256, cHH = 256, cH = 512, cT = 22;
constexpr int cG1 = 4 * cHH, cG2 = 4 * cH, cM = cS * cB;
constexpr int START_TAG = cT - 2, STOP_TAG = cT - 1;

__device__ __align__(16) float d_x[(size_t)cM * cE];
__device__ __align__(16) float d_gxf[(size_t)cM * cG1];
__device__ __align__(16) float d_gxb[(size_t)cM * cG1];
__device__ __align__(16) float d_bi[(size_t)cM * cH];
__device__ __align__(16) float d_g0in[(size_t)cM * cG2];
__device__ __align__(16) float d_outs[(size_t)cM * cH];
__device__ __align__(16) float d_feats[(size_t)cM * cT];
__device__ __align__(16) float d_hfB[2][cHH * cB];
__device__ __align__(16) float d_hbB[2][cHH * cB];
__device__ __align__(16) float d_h0B[2][cH * cB];
__device__ __align__(16) float d_h1B[2][cH * cB];
__device__ volatile unsigned d_arr[3][128 * 32];

__device__ __forceinline__ float sigm(float x) { return 1.0f / (1.0f + expf(-x)); }
__device__ __forceinline__ unsigned long long ffma2(unsigned long long a, unsigned long long b, unsigned long long c) {
    unsigned long long d;
    asm("fma.rn.f32x2 %0, %1, %2, %3;" : "=l"(d) : "l"(a), "l"(b), "l"(c));
    return d;
}
__device__ __forceinline__ float pairsum(unsigned long long v) {
    float lo, hi;
    asm("mov.b64 {%0,%1}, %2;" : "=f"(lo), "=f"(hi) : "l"(v));
    return lo + hi;
}
__device__ __forceinline__ unsigned long long pack2(float x) {
    unsigned long long d;
    asm("mov.b64 %0, {%1,%1};" : "=l"(d) : "f"(x));
    return d;
}
__device__ __forceinline__ ulonglong2 ldcg128(const float* p) {
    ulonglong2 v;
    asm volatile("ld.global.cg.v2.u64 {%0,%1}, [%2];" : "=l"(v.x), "=l"(v.y) : "l"(p));
    return v;
}
__device__ __forceinline__ void gbar(int ch, int base, int n, unsigned phase) {
    __threadfence();
    __syncthreads();
    if (threadIdx.x == 0) d_arr[ch][blockIdx.x * 32] = phase;
    if ((int)threadIdx.x < n)
        while (d_arr[ch][(base + threadIdx.x) * 32] < phase) { }
    __threadfence();
    __syncthreads();
}

__global__ void init_kernel(const float* __restrict__ h1_0, const float* __restrict__ h2_0) {
    int g = blockIdx.x * blockDim.x + threadIdx.x, st = gridDim.x * blockDim.x;
    for (int i = g; i < 3 * 128 * 32; i += st) ((volatile unsigned*)d_arr)[i] = 0u;
    for (int i = g; i < cHH * cB; i += st) {
        int k = i >> 6, b = i & 63, a = (k >> 1) * 128 + b * 2 + (k & 1);
        d_hfB[0][a] = h1_0[k];
        d_hbB[0][a] = h1_0[cHH + k];
    }
    for (int i = g; i < cH * cB; i += st) {
        int k = i >> 6, b = i & 63, a = (k >> 1) * 128 + b * 2 + (k & 1);
        d_h0B[1][a] = h2_0[k];
        d_h1B[0][a] = h2_0[cH + k];
    }
}

__global__ void gather_kernel(const int* __restrict__ sentence, const float* __restrict__ emb) {
    int row = blockIdx.x, b = row & 63, s = row >> 6;
    int tok = sentence[b * cS + s];
    d_x[(size_t)row * cE + threadIdx.x] = emb[(size_t)tok * cE + threadIdx.x];
}

// C[M,N] = A @ W^T + bias ; 128x128, f32x2, W prefetched; z selects pair.
__global__ __launch_bounds__(256, 2) void gemmT(
    const float* __restrict__ A, const float* __restrict__ W0, const float* __restrict__ W1,
    const float* __restrict__ b0, const float* __restrict__ b1,
    float* __restrict__ C0, float* __restrict__ C1, int M, int N, int K) {
    const float* W = blockIdx.z ? W1 : W0;
    const float* bias = blockIdx.z ? b1 : b0;
    float* C = blockIdx.z ? C1 : C0;
    __shared__ __align__(16) float As[16][136];
    __shared__ __align__(16) float Ws[16][136];
    const int tid = threadIdx.x;
    const int mB = blockIdx.y * 128, nB = blockIdx.x * 128;
    const int tm = tid >> 4, tn = tid & 15;
    const int r = tid >> 1, c = (tid & 1) * 8;
    unsigned long long acc[32];
#pragma unroll
    for (int i = 0; i < 32; i++) acc[i] = 0ull;
    const int nt = K >> 4;
    float4 w0 = *(const float4*)&W[(size_t)(nB + r) * K + c];
    float4 w1 = *(const float4*)&W[(size_t)(nB + r) * K + c + 4];
    for (int kt = 0; kt < nt; kt++) {
        const int k0 = kt << 4;
        float4 a0 = *(const float4*)&A[(size_t)(mB + r) * K + k0 + c];
        float4 a1 = *(const float4*)&A[(size_t)(mB + r) * K + k0 + c + 4];
        __syncthreads();
        As[c+0][r]=a0.x; As[c+1][r]=a0.y; As[c+2][r]=a0.z; As[c+3][r]=a0.w;
        As[c+4][r]=a1.x; As[c+5][r]=a1.y; As[c+6][r]=a1.z; As[c+7][r]=a1.w;
        Ws[c+0][r]=w0.x; Ws[c+1][r]=w0.y; Ws[c+2][r]=w0.z; Ws[c+3][r]=w0.w;
        Ws[c+4][r]=w1.x; Ws[c+5][r]=w1.y; Ws[c+6][r]=w1.z; Ws[c+7][r]=w1.w;
        __syncthreads();
        if (kt + 1 < nt) {
            w0 = *(const float4*)&W[(size_t)(nB + r) * K + k0 + 16 + c];
            w1 = *(const float4*)&W[(size_t)(nB + r) * K + k0 + 16 + c + 4];
        }
#pragma unroll
        for (int k = 0; k < 16; k++) {
            ulonglong2 am0 = *(const ulonglong2*)&As[k][tm * 8];
            ulonglong2 am1 = *(const ulonglong2*)&As[k][tm * 8 + 4];
            float4 wn0 = *(const float4*)&Ws[k][tn * 8];
            float4 wn1 = *(const float4*)&Ws[k][tn * 8 + 4];
            unsigned long long wp[8];
            wp[0]=pack2(wn0.x); wp[1]=pack2(wn0.y); wp[2]=pack2(wn0.z); wp[3]=pack2(wn0.w);
            wp[4]=pack2(wn1.x); wp[5]=pack2(wn1.y); wp[6]=pack2(wn1.z); wp[7]=pack2(wn1.w);
            unsigned long long ap[4] = {am0.x, am0.y, am1.x, am1.y};
#pragma unroll
            for (int mp = 0; mp < 4; mp++)
#pragma unroll
                for (int n = 0; n < 8; n++)
                    acc[mp * 8 + n] = ffma2(ap[mp], wp[n], acc[mp * 8 + n]);
        }
    }
#pragma unroll
    for (int mp = 0; mp < 4; mp++) {
        int m = mB + tm * 8 + mp * 2;
#pragma unroll
        for (int n = 0; n < 8; n++) {
            int nn = nB + tn * 8 + n;
            float lo, hi;
            asm("mov.b64 {%0,%1}, %2;" : "=f"(lo), "=f"(hi) : "l"(acc[mp * 8 + n]));
            float bv = bias[nn];
            C[(size_t)m * N + nn] = lo + bv;
            C[(size_t)(m + 1) * N + nn] = hi + bv;
        }
    }
}

// tag head: feats[m][t] = dot(outs[m], W_tag[t]) + b_tag[t]
__global__ __launch_bounds__(256) void tag_head(
    const float* __restrict__ W_tag, const float* __restrict__ b_tag) {
    __shared__ __align__(16) float wT[cH][24];
    __shared__ __align__(16) float rowbuf[8][cH];
    const int tid = threadIdx.x, wid = tid >> 5, lane = tid & 31;
    for (int i = tid; i < cT * cH; i += 256) {
        int t = i >> 9, k = i & 511;
        wT[k][t] = W_tag[i];
    }
    __syncthreads();
    float bt = (lane < cT) ? b_tag[lane] : 0.f;
    for (int rr = 0; rr < 16; rr++) {
        int m = blockIdx.x * 128 + wid * 16 + rr;
        const float4* src = (const float4*)&d_outs[(size_t)m * cH];
        float4* dst = (float4*)&rowbuf[wid][0];
#pragma unroll
        for (int q = 0; q < 4; q++) dst[lane + q * 32] = src[lane + q * 32];
        __syncwarp();
        float acc = 0.f;
        if (lane < cT) {
#pragma unroll 8
            for (int k = 0; k < cH; k++) acc += rowbuf[wid][k] * wT[k][lane];
        }
        __syncwarp();
        if (lane < cT) d_feats[(size_t)m * cT + lane] = acc + bt;
    }
}

// 8-gate matvec: acc[g*4+j], wr offset by gate-half gh
__device__ __forceinline__ void mv8(unsigned long long* acc, const float* __restrict__ hsrc,
                                    const float2* __restrict__ wsm, int k0, int k1, int wb,
                                    int bg, int gh) {
    ulonglong2 hA = ldcg128(hsrc + (size_t)k0 * 128 + bg * 8);
    ulonglong2 hB = ldcg128(hsrc + (size_t)k0 * 128 + bg * 8 + 4);
    for (int kp = k0; kp < k1; ++kp) {
        ulonglong2 cA = hA, cB = hB;
        if (kp + 1 < k1) {
            hA = ldcg128(hsrc + (size_t)(kp + 1) * 128 + bg * 8);
            hB = ldcg128(hsrc + (size_t)(kp + 1) * 128 + bg * 8 + 4);
        }
        const unsigned long long* wr =
            (const unsigned long long*)(wsm + (wb + kp) * 17) + gh * 8;
#pragma unroll
        for (int g = 0; g < 8; ++g) {
            unsigned long long w = wr[g];
            acc[g * 4 + 0] = ffma2(cA.x, w, acc[g * 4 + 0]);
            acc[g * 4 + 1] = ffma2(cA.y, w, acc[g * 4 + 1]);
            acc[g * 4 + 2] = ffma2(cB.x, w, acc[g * 4 + 2]);
            acc[g * 4 + 3] = ffma2(cB.y, w, acc[g * 4 + 3]);
        }
    }
}
// red: [16 warp][8 g][64 b]; shfl(16) merges the ks-pair inside each warp
__device__ __forceinline__ void red_store8(float* red, unsigned long long* acc) {
    const int lane = threadIdx.x & 31, ws = threadIdx.x >> 5;
#pragma unroll
    for (int g = 0; g < 8; ++g) {
        float v0 = pairsum(acc[g * 4 + 0]);
        float v1 = pairsum(acc[g * 4 + 1]);
        float v2 = pairsum(acc[g * 4 + 2]);
        float v3 = pairsum(acc[g * 4 + 3]);
        v0 += __shfl_xor_sync(0xffffffffu, v0, 16);
        v1 += __shfl_xor_sync(0xffffffffu, v1, 16);
        v2 += __shfl_xor_sync(0xffffffffu, v2, 16);
        v3 += __shfl_xor_sync(0xffffffffu, v3, 16);
        if (lane < 16)
            *(float4*)&red[((size_t)ws * 8 + g) * 64 + lane * 4] = make_float4(v0, v1, v2, v3);
    }
}
// gate jl handled by warps [ (jl>=8?8:0) .. +8 ), local row jl&7
__device__ __forceinline__ float gsum8(const float* red, int jl, int cb) {
    const int base = (jl >> 3) * 8, gl = jl & 7;
    float v = 0.f;
#pragma unroll
    for (int w = 0; w < 8; ++w) v += red[((size_t)(base + w) * 8 + gl) * 64 + cb];
    return v;
}

__global__ __launch_bounds__(512, 1) void bilstm_scan(
    const float* __restrict__ whh_f, const float* __restrict__ whh_b,
    const float* __restrict__ c1_0, const float* __restrict__ h1_0,
    const int* __restrict__ lengths) {
    extern __shared__ float smx[];
    float2* w = (float2*)smx;             // [128][17]
    float* red = (float*)(w + 128 * 17);  // [16][8][64]
    const int tid = threadIdx.x;
    const int dir = blockIdx.x >> 6;
    const int hb4 = (blockIdx.x & 63) * 4;
    const float* whh = dir ? whh_b : whh_f;
    const float* gin_base = dir ? d_gxb : d_gxf;

    for (int i = tid; i < 128 * 16; i += 512) {
        int jl = i >> 7, kp = i & 127;
        int j = (jl >> 2) * cHH + hb4 + (jl & 3);
        w[kp * 17 + jl] = *(const float2*)&whh[(size_t)j * cHH + 2 * kp];
    }
    const int bg = tid & 15, ks = (tid >> 4) & 15, gh = tid >> 8;
    const bool cellth = tid < 256;
    const int cb = tid & 63, chl = (tid >> 6) & 3, chh = hb4 + chl;
    float cReg = 0.f, hPrev = 0.f;
    int len = 0;
    if (cellth) {
        cReg = c1_0[dir * cHH + chh];
        hPrev = h1_0[dir * cHH + chh];
        len = lengths[cb];
    }
    __syncthreads();

    for (int t = 0; t < cS; ++t) {
        const int s = dir ? (cS - 1 - t) : t;
        const int p = t & 1;
        unsigned long long acc[32];
#pragma unroll
        for (int i = 0; i < 32; i++) acc[i] = 0ull;
        mv8(acc, dir ? d_hbB[p] : d_hfB[p], w, ks * 8, ks * 8 + 8, 0, bg, gh);
        red_store8(red, acc);
        __syncthreads();

        if (cellth) {
            const float* gin = gin_base + ((size_t)(s * 64 + cb)) * cG1;
            float gi = gsum8(red, 0 + chl, cb) + gin[0 * cHH + chh];
            float gf = gsum8(red, 4 + chl, cb) + gin[1 * cHH + chh];
            float gg = gsum8(red, 8 + chl, cb) + gin[2 * cHH + chh];
            float go = gsum8(red, 12 + chl, cb) + gin[3 * cHH + chh];
            float c2 = sigm(gf) * cReg + sigm(gi) * tanhf(gg);
            float h2 = sigm(go) * tanhf(c2);
            bool m = s < len;
            float hn = m ? h2 : hPrev;
            if (m) cReg = c2;
            hPrev = hn;
            (dir ? d_hbB[p ^ 1] : d_hfB[p ^ 1])[(chh >> 1) * 128 + cb * 2 + (chh & 1)] = hn;
            d_bi[((size_t)(s * 64 + cb)) * cH + dir * cHH + chh] = m ? h2 : 0.0f;
        }
        if (t < cS - 1) gbar(dir, dir * 64, 64, (unsigned)(t + 1));
    }
}

__global__ __launch_bounds__(512, 1) void stacked_scan(
    const float* __restrict__ wih_s, const float* __restrict__ whh_s,
    const float* __restrict__ b_s, const float* __restrict__ c2_0) {
    extern __shared__ float smx[];
    float2* w0 = (float2*)smx;             // [256][17]
    float2* w1 = w0 + 256 * 17;            // [512][17]
    float* red1 = (float*)(w1 + 512 * 17); // [16][8][64]
    float* red0 = red1 + 16 * 8 * 64;
    const int tid = threadIdx.x;
    const int hb4 = blockIdx.x * 4;

    for (int i = tid; i < 256 * 16; i += 512) {
        int jl = i >> 8, kp = i & 255;
        int j = (jl >> 2) * cH + hb4 + (jl & 3);
        w0[kp * 17 + jl] = *(const float2*)&whh_s[(size_t)j * cH + 2 * kp];
    }
    for (int i = tid; i < 512 * 16; i += 512) {
        int jl = i >> 9, kp = i & 511;
        int j = (jl >> 2) * cH + hb4 + (jl & 3);
        float2 v;
        if (kp < 256) v = *(const float2*)&wih_s[(size_t)(cG2 + j) * cH + 2 * kp];
        else v = *(const float2*)&whh_s[(size_t)(cG2 + j) * cH + 2 * (kp - 256)];
        w1[kp * 17 + jl] = v;
    }
    const int bg = tid & 15, ks = (tid >> 4) & 15, gh = tid >> 8;
    const bool cellth = tid < 256;
    const int cb = tid & 63, chl = (tid >> 6) & 3, chh = hb4 + chl;
    float c0 = 0.f, c1 = 0.f;
    float bias1[4] = {0.f, 0.f, 0.f, 0.f};
    if (cellth) {
        c0 = c2_0[chh];
        c1 = c2_0[cH + chh];
#pragma unroll
        for (int g = 0; g < 4; g++) bias1[g] = b_s[cG2 + g * cH + chh];
    }
    __syncthreads();

    for (int t = -1; t < cS; ++t) {
        const int p = t & 1;
        unsigned long long acc[32];
        if (t >= 0) {  // L1(t): K=1024 over [h0new(t) | h1(t-1)]
#pragma unroll
            for (int i = 0; i < 32; i++) acc[i] = 0ull;
            if (ks < 8) mv8(acc, d_h0B[p], w1, ks * 32, ks * 32 + 32, 0, bg, gh);
            else        mv8(acc, d_h1B[p], w1, (ks - 8) * 32, (ks - 8) * 32 + 32, 256, bg, gh);
            red_store8(red1, acc);
        }
        if (t < cS - 1) {  // L0(t+1): K=512 over h0new(t)
#pragma unroll
            for (int i = 0; i < 32; i++) acc[i] = 0ull;
            mv8(acc, d_h0B[p], w0, ks * 16, ks * 16 + 16, 0, bg, gh);
            red_store8(red0, acc);
        }
        __syncthreads();

        if (cellth) {
            if (t >= 0) {
                float gi = gsum8(red1, 0 + chl, cb) + bias1[0];
                float gf = gsum8(red1, 4 + chl, cb) + bias1[1];
                float gg = gsum8(red1, 8 + chl, cb) + bias1[2];
                float go = gsum8(red1, 12 + chl, cb) + bias1[3];
                c1 = sigm(gf) * c1 + sigm(gi) * tanhf(gg);
                float h1v = sigm(go) * tanhf(c1);
                d_h1B[p ^ 1][(chh >> 1) * 128 + cb * 2 + (chh & 1)] = h1v;
                d_outs[((size_t)(t * 64 + cb)) * cH + chh] = h1v;
            }
            if (t < cS - 1) {
                const float* gin = d_g0in + ((size_t)((t + 1) * 64 + cb)) * cG2;
                float gi = gsum8(red0, 0 + chl, cb) + gin[0 * cH + chh];
                float gf = gsum8(red0, 4 + chl, cb) + gin[1 * cH + chh];
                float gg = gsum8(red0, 8 + chl, cb) + gin[2 * cH + chh];
                float go = gsum8(red0, 12 + chl, cb) + gin[3 * cH + chh];
                c0 = sigm(gf) * c0 + sigm(gi) * tanhf(gg);
                float h0v = sigm(go) * tanhf(c0);
                d_h0B[p ^ 1][(chh >> 1) * 128 + cb * 2 + (chh & 1)] = h0v;
            }
        }
        if (t < cS - 1) gbar(2, 0, 128, (unsigned)(t + 2));
    }
}

__global__ __launch_bounds__(32) void viterbi_kernel(
    const int* __restrict__ lengths, const float* __restrict__ trans, float* __restrict__ outp) {
    __shared__ float score_sm[cT];
    __shared__ uint8_t bp_sm[cS - 1][cT];
    const int b = blockIdx.x, i = threadIdx.x;
    const int len = lengths[b];
    float trow[cT];
    if (i < cT) {
#pragma unroll
        for (int j = 0; j < cT; j++) trow[j] = trans[i * cT + j];
        score_sm[i] = d_feats[(size_t)b * cT + i] + trow[START_TAG];
    }
    __syncwarp();
    for (int s = 1; s < cS; s++) {
        float ft = 0.f;
        if (i < cT) ft = d_feats[((size_t)s * cB + b) * cT + i];
        bool m = s < len;
        float best = -1e30f;
        int bj = 0;
        if (i < cT) {
#pragma unroll
            for (int j = 0; j < cT; j++) {
                float c = score_sm[j] + trow[j];
                if (c > best) { best = c; bj = j; }
            }
        }
        __syncwarp();
        if (i < cT) {
            if (m) score_sm[i] = best + ft;
            bp_sm[s - 1][i] = (uint8_t)(m ? bj : i);
        }
        __syncwarp();
    }
    if (i == 0) {
        float best = -1e30f;
        int bt = 0;
        for (int t = 0; t < cT; t++) {
            float v = score_sm[t] + trans[STOP_TAG * cT + t];
            if (v > best) { best = v; bt = t; }
        }
        outp[b] = best;
        int tag = bt;
        outp[cB + (size_t)b * cS + (cS - 1)] = (float)tag;
        for (int s = cS - 2; s >= 0; s--) {
            tag = bp_sm[s][tag];
            outp[cB + (size_t)b * cS + s] = (float)tag;
        }
    }
}

extern "C" void kernel_launch(void* const* d_in, const int* in_sizes, int n_in,
                              void* d_out, int out_size) {
    const int*   sentence = (const int*)  d_in[0];
    const int*   lengths  = (const int*)  d_in[1];
    const float* emb      = (const float*)d_in[2];
    const float* wih_f    = (const float*)d_in[3];
    const float* whh_f    = (const float*)d_in[4];
    const float* b_f      = (const float*)d_in[5];
    const float* wih_b    = (const float*)d_in[6];
    const float* whh_b    = (const float*)d_in[7];
    const float* b_b      = (const float*)d_in[8];
    const float* h1_0     = (const float*)d_in[9];
    const float* c1_0     = (const float*)d_in[10];
    const float* wih_s    = (const float*)d_in[11];
    const float* whh_s    = (const float*)d_in[12];
    const float* b_s      = (const float*)d_in[13];
    const float* h2_0     = (const float*)d_in[14];
    const float* c2_0     = (const float*)d_in[15];
    const float* W_tag    = (const float*)d_in[16];
    const float* b_tag    = (const float*)d_in[17];
    const float* trans    = (const float*)d_in[18];
    float* outp = (float*)d_out;

    const int smemBi = 128 * 17 * 8 + 16 * 8 * 64 * 4;                    // 50176
    const int smemSt = (256 * 17 + 512 * 17) * 8 + 2 * 16 * 8 * 64 * 4;   // 169984
    static bool done = false;
    if (!done) {
        cudaFuncSetAttribute(bilstm_scan, cudaFuncAttributeMaxDynamicSharedMemorySize, smemBi);
        cudaFuncSetAttribute(stacked_scan, cudaFuncAttributeMaxDynamicSharedMemorySize, smemSt);
        done = true;
    }
    float *xbuf, *gxf, *gxb, *bibuf, *g0in;
    cudaGetSymbolAddress((void**)&xbuf, d_x);
    cudaGetSymbolAddress((void**)&gxf, d_gxf);
    cudaGetSymbolAddress((void**)&gxb, d_gxb);
    cudaGetSymbolAddress((void**)&bibuf, d_bi);
    cudaGetSymbolAddress((void**)&g0in, d_g0in);

    init_kernel<<<64, 256>>>(h1_0, h2_0);
    gather_kernel<<<cM, cE>>>(sentence, emb);
    dim3 g1(cG1 / 128, cM / 128, 2);
    gemmT<<<g1, 256>>>(xbuf, wih_f, wih_b, b_f, b_b, gxf, gxb, cM, cG1, cE);
    bilstm_scan<<<128, 512, smemBi>>>(whh_f, whh_b, c1_0, h1_0, lengths);
    dim3 g2(cG2 / 128, cM / 128, 1);
    gemmT<<<g2, 256>>>(bibuf, wih_s, wih_s, b_s, b_s, g0in, g0in, cM, cG2, cH);
    stacked_scan<<<128, 512, smemSt>>>(wih_s, whh_s, b_s, c2_0);
    tag_head<<<cM / 128, 256>>>(W_tag, b_tag);
    viterbi_kernel<<<cB, 32>>>(lengths, trans, outp);
}

// round 17
// speedup vs baseline: 1.0973x; 1.0973x over previous
#include <cuda_runtime.h>
#include <stdint.h>
#include <math.h>

constexpr int cS = 512, cB = 64, cE = 256, cHH = 256, cH = 512, cT = 22;
constexpr int cG1 = 4 * cHH, cG2 = 4 * cH, cM = cS * cB;
constexpr int START_TAG = cT - 2, STOP_TAG = cT - 1;

__device__ __align__(16) float d_x[(size_t)cM * cE];
__device__ __align__(16) float d_gxf[(size_t)cM * cG1];
__device__ __align__(16) float d_gxb[(size_t)cM * cG1];
__device__ __align__(16) float d_bi[(size_t)cM * cH];
__device__ __align__(16) float d_g0in[(size_t)cM * cG2];
__device__ __align__(16) float d_outs[(size_t)cM * cH];
__device__ __align__(16) float d_feats[(size_t)cM * cT];
__device__ __align__(16) float d_hfB[2][cHH * cB];
__device__ __align__(16) float d_hbB[2][cHH * cB];
__device__ __align__(16) float d_h0B[2][cH * cB];
__device__ __align__(16) float d_h1B[2][cH * cB];
__device__ volatile unsigned d_arr[3][128 * 32];

__device__ __forceinline__ float sigm(float x) { return 1.0f / (1.0f + expf(-x)); }
__device__ __forceinline__ unsigned long long ffma2(unsigned long long a, unsigned long long b, unsigned long long c) {
    unsigned long long d;
    asm("fma.rn.f32x2 %0, %1, %2, %3;" : "=l"(d) : "l"(a), "l"(b), "l"(c));
    return d;
}
__device__ __forceinline__ float pairsum(unsigned long long v) {
    float lo, hi;
    asm("mov.b64 {%0,%1}, %2;" : "=f"(lo), "=f"(hi) : "l"(v));
    return lo + hi;
}
__device__ __forceinline__ unsigned long long pack2(float x) {
    unsigned long long d;
    asm("mov.b64 %0, {%1,%1};" : "=l"(d) : "f"(x));
    return d;
}
__device__ __forceinline__ ulonglong2 ldcg128(const float* p) {
    ulonglong2 v;
    asm volatile("ld.global.cg.v2.u64 {%0,%1}, [%2];" : "=l"(v.x), "=l"(v.y) : "l"(p));
    return v;
}
__device__ __forceinline__ float ldg32(const float* p) {
    float v;
    asm volatile("ld.global.ca.f32 %0, [%1];" : "=f"(v) : "l"(p));
    return v;
}
__device__ __forceinline__ void gbar(int ch, int base, int n, unsigned phase) {
    __threadfence();
    __syncthreads();
    if (threadIdx.x == 0) d_arr[ch][blockIdx.x * 32] = phase;
    if ((int)threadIdx.x < n)
        while (d_arr[ch][(base + threadIdx.x) * 32] < phase) { }
    __threadfence();
    __syncthreads();
}

__global__ void init_kernel(const float* __restrict__ h1_0, const float* __restrict__ h2_0) {
    int g = blockIdx.x * blockDim.x + threadIdx.x, st = gridDim.x * blockDim.x;
    for (int i = g; i < 3 * 128 * 32; i += st) ((volatile unsigned*)d_arr)[i] = 0u;
    for (int i = g; i < cHH * cB; i += st) {
        int k = i >> 6, b = i & 63, a = (k >> 1) * 128 + b * 2 + (k & 1);
        d_hfB[0][a] = h1_0[k];
        d_hbB[0][a] = h1_0[cHH + k];
    }
    for (int i = g; i < cH * cB; i += st) {
        int k = i >> 6, b = i & 63, a = (k >> 1) * 128 + b * 2 + (k & 1);
        d_h0B[1][a] = h2_0[k];
        d_h1B[0][a] = h2_0[cH + k];
    }
}

__global__ void gather_kernel(const int* __restrict__ sentence, const float* __restrict__ emb) {
    int row = blockIdx.x, b = row & 63, s = row >> 6;
    int tok = sentence[b * cS + s];
    d_x[(size_t)row * cE + threadIdx.x] = emb[(size_t)tok * cE + threadIdx.x];
}

// C[M,N] = A[M,K] @ W[N,K]^T + bias ; 128x128 tile, f32x2, W prefetched
__global__ __launch_bounds__(256, 2) void gemmT(
    const float* __restrict__ A, const float* __restrict__ W,
    const float* __restrict__ bias, float* __restrict__ C, int M, int N, int K) {
    __shared__ __align__(16) float As[16][136];
    __shared__ __align__(16) float Ws[16][136];
    const int tid = threadIdx.x;
    const int mB = blockIdx.y * 128, nB = blockIdx.x * 128;
    const int tm = tid >> 4, tn = tid & 15;
    const int r = tid >> 1, c = (tid & 1) * 8;
    unsigned long long acc[32];
#pragma unroll
    for (int i = 0; i < 32; i++) acc[i] = 0ull;

    const int nt = K >> 4;
    float4 w0 = make_float4(0.f, 0.f, 0.f, 0.f), w1 = w0;
    if (nB + r < N) {
        w0 = *(const float4*)&W[(size_t)(nB + r) * K + c];
        w1 = *(const float4*)&W[(size_t)(nB + r) * K + c + 4];
    }
    for (int kt = 0; kt < nt; kt++) {
        const int k0 = kt << 4;
        float4 a0 = *(const float4*)&A[(size_t)(mB + r) * K + k0 + c];
        float4 a1 = *(const float4*)&A[(size_t)(mB + r) * K + k0 + c + 4];
        __syncthreads();
        As[c+0][r]=a0.x; As[c+1][r]=a0.y; As[c+2][r]=a0.z; As[c+3][r]=a0.w;
        As[c+4][r]=a1.x; As[c+5][r]=a1.y; As[c+6][r]=a1.z; As[c+7][r]=a1.w;
        Ws[c+0][r]=w0.x; Ws[c+1][r]=w0.y; Ws[c+2][r]=w0.z; Ws[c+3][r]=w0.w;
        Ws[c+4][r]=w1.x; Ws[c+5][r]=w1.y; Ws[c+6][r]=w1.z; Ws[c+7][r]=w1.w;
        __syncthreads();
        if (kt + 1 < nt) {
            w0 = make_float4(0.f, 0.f, 0.f, 0.f); w1 = w0;
            if (nB + r < N) {
                w0 = *(const float4*)&W[(size_t)(nB + r) * K + k0 + 16 + c];
                w1 = *(const float4*)&W[(size_t)(nB + r) * K + k0 + 16 + c + 4];
            }
        }
#pragma unroll
        for (int k = 0; k < 16; k++) {
            ulonglong2 am0 = *(const ulonglong2*)&As[k][tm * 8];
            ulonglong2 am1 = *(const ulonglong2*)&As[k][tm * 8 + 4];
            float4 wn0 = *(const float4*)&Ws[k][tn * 8];
            float4 wn1 = *(const float4*)&Ws[k][tn * 8 + 4];
            unsigned long long wp[8];
            wp[0]=pack2(wn0.x); wp[1]=pack2(wn0.y); wp[2]=pack2(wn0.z); wp[3]=pack2(wn0.w);
            wp[4]=pack2(wn1.x); wp[5]=pack2(wn1.y); wp[6]=pack2(wn1.z); wp[7]=pack2(wn1.w);
            unsigned long long ap[4] = {am0.x, am0.y, am1.x, am1.y};
#pragma unroll
            for (int mp = 0; mp < 4; mp++)
#pragma unroll
                for (int n = 0; n < 8; n++)
                    acc[mp * 8 + n] = ffma2(ap[mp], wp[n], acc[mp * 8 + n]);
        }
    }
#pragma unroll
    for (int mp = 0; mp < 4; mp++) {
        int m = mB + tm * 8 + mp * 2;
#pragma unroll
        for (int n = 0; n < 8; n++) {
            int nn = nB + tn * 8 + n;
            if (nn < N) {
                float lo, hi;
                asm("mov.b64 {%0,%1}, %2;" : "=f"(lo), "=f"(hi) : "l"(acc[mp * 8 + n]));
                float bv = bias[nn];
                C[(size_t)m * N + nn] = lo + bv;
                C[(size_t)(m + 1) * N + nn] = hi + bv;
            }
        }
    }
}

// depth-1 prefetch matvec (R5-best form)
__device__ __forceinline__ void mv(unsigned long long* acc, const float* __restrict__ hsrc,
                                   const float2* __restrict__ wsm, int k0, int k1, int wb, int bg) {
    ulonglong2 hA = ldcg128(hsrc + (size_t)k0 * 128 + bg * 8);
    ulonglong2 hB = ldcg128(hsrc + (size_t)k0 * 128 + bg * 8 + 4);
    for (int kp = k0; kp < k1; ++kp) {
        ulonglong2 cA = hA, cB = hB;
        if (kp + 1 < k1) {
            hA = ldcg128(hsrc + (size_t)(kp + 1) * 128 + bg * 8);
            hB = ldcg128(hsrc + (size_t)(kp + 1) * 128 + bg * 8 + 4);
        }
        const unsigned long long* wr = (const unsigned long long*)(wsm + (wb + kp) * 17);
#pragma unroll
        for (int g = 0; g < 16; ++g) {
            unsigned long long w = wr[g];
            acc[g * 4 + 0] = ffma2(cA.x, w, acc[g * 4 + 0]);
            acc[g * 4 + 1] = ffma2(cA.y, w, acc[g * 4 + 1]);
            acc[g * 4 + 2] = ffma2(cB.x, w, acc[g * 4 + 2]);
            acc[g * 4 + 3] = ffma2(cB.y, w, acc[g * 4 + 3]);
        }
    }
}

__device__ __forceinline__ void red_store(float* red, unsigned long long* acc) {
    const int lane = threadIdx.x & 31, wid = threadIdx.x >> 5;
#pragma unroll
    for (int g = 0; g < 16; ++g) {
        float v0 = pairsum(acc[g * 4 + 0]);
        float v1 = pairsum(acc[g * 4 + 1]);
        float v2 = pairsum(acc[g * 4 + 2]);
        float v3 = pairsum(acc[g * 4 + 3]);
        v0 += __shfl_xor_sync(0xffffffffu, v0, 16);
        v1 += __shfl_xor_sync(0xffffffffu, v1, 16);
        v2 += __shfl_xor_sync(0xffffffffu, v2, 16);
        v3 += __shfl_xor_sync(0xffffffffu, v3, 16);
        if (lane < 16)
            *(float4*)&red[(wid * 16 + g) * 64 + lane * 4] = make_float4(v0, v1, v2, v3);
    }
}
__device__ __forceinline__ float gsum(const float* red, int g, int cb) {
    float v = 0.f;
#pragma unroll
    for (int w = 0; w < 8; ++w) v += red[(w * 16 + g) * 64 + cb];
    return v;
}

__global__ __launch_bounds__(256, 1) void bilstm_scan(
    const float* __restrict__ whh_f, const float* __restrict__ whh_b,
    const float* __restrict__ c1_0, const float* __restrict__ h1_0,
    const int* __restrict__ lengths) {
    extern __shared__ float smx[];
    float2* w = (float2*)smx;
    float* red = (float*)(w + 128 * 17);
    const int tid = threadIdx.x;
    const int dir = blockIdx.x >> 6;
    const int hb4 = (blockIdx.x & 63) * 4;
    const float* whh = dir ? whh_b : whh_f;
    const float* gin_base = dir ? d_gxb : d_gxf;

    for (int i = tid; i < 128 * 16; i += 256) {
        int jl = i >> 7, kp = i & 127;
        int j = (jl >> 2) * cHH + hb4 + (jl & 3);
        w[kp * 17 + jl] = *(const float2*)&whh[(size_t)j * cHH + 2 * kp];
    }
    const int bg = tid & 15, ks = tid >> 4;
    const int cb = tid & 63, chl = tid >> 6, chh = hb4 + chl;
    float cReg = c1_0[dir * cHH + chh];
    float hPrev = h1_0[dir * cHH + chh];
    const int len = lengths[cb];
    __syncthreads();

    for (int t = 0; t < cS; ++t) {
        const int s = dir ? (cS - 1 - t) : t;
        const int p = t & 1;
        // prefetch gin[s] (h-independent) so its latency hides under mv
        const float* gin = gin_base + ((size_t)(s * 64 + cb)) * cG1;
        float pg0 = ldg32(gin + 0 * cHH + chh);
        float pg1 = ldg32(gin + 1 * cHH + chh);
        float pg2 = ldg32(gin + 2 * cHH + chh);
        float pg3 = ldg32(gin + 3 * cHH + chh);

        unsigned long long acc[64];
#pragma unroll
        for (int i = 0; i < 64; i++) acc[i] = 0ull;
        mv(acc, dir ? d_hbB[p] : d_hfB[p], w, ks * 8, ks * 8 + 8, 0, bg);
        red_store(red, acc);
        __syncthreads();

        float gi = gsum(red, 0 + chl, cb) + pg0;
        float gf = gsum(red, 4 + chl, cb) + pg1;
        float gg = gsum(red, 8 + chl, cb) + pg2;
        float go = gsum(red, 12 + chl, cb) + pg3;
        float c2 = sigm(gf) * cReg + sigm(gi) * tanhf(gg);
        float h2 = sigm(go) * tanhf(c2);
        bool m = s < len;
        float hn = m ? h2 : hPrev;
        if (m) cReg = c2;
        hPrev = hn;
        (dir ? d_hbB[p ^ 1] : d_hfB[p ^ 1])[(chh >> 1) * 128 + cb * 2 + (chh & 1)] = hn;
        d_bi[((size_t)(s * 64 + cb)) * cH + dir * cHH + chh] = m ? h2 : 0.0f;
        if (t < cS - 1) gbar(dir, dir * 64, 64, (unsigned)(t + 1));
    }
}

__global__ __launch_bounds__(256, 1) void stacked_scan(
    const float* __restrict__ wih_s, const float* __restrict__ whh_s,
    const float* __restrict__ b_s, const float* __restrict__ c2_0) {
    extern __shared__ float smx[];
    float2* w0 = (float2*)smx;
    float2* w1 = w0 + 256 * 17;
    float* red1 = (float*)(w1 + 512 * 17);
    float* red0 = red1 + 8 * 16 * 64;
    const int tid = threadIdx.x;
    const int hb4 = blockIdx.x * 4;

    for (int i = tid; i < 256 * 16; i += 256) {
        int jl = i >> 8, kp = i & 255;
        int j = (jl >> 2) * cH + hb4 + (jl & 3);
        w0[kp * 17 + jl] = *(const float2*)&whh_s[(size_t)j * cH + 2 * kp];
    }
    for (int i = tid; i < 512 * 16; i += 256) {
        int jl = i >> 9, kp = i & 511;
        int j = (jl >> 2) * cH + hb4 + (jl & 3);
        float2 v;
        if (kp < 256) v = *(const float2*)&wih_s[(size_t)(cG2 + j) * cH + 2 * kp];
        else v = *(const float2*)&whh_s[(size_t)(cG2 + j) * cH + 2 * (kp - 256)];
        w1[kp * 17 + jl] = v;
    }
    const int bg = tid & 15, ks = tid >> 4;
    const int cb = tid & 63, chl = tid >> 6, chh = hb4 + chl;
    float c0 = c2_0[chh], c1 = c2_0[cH + chh];
    float bias1[4];
#pragma unroll
    for (int g = 0; g < 4; g++) bias1[g] = b_s[cG2 + g * cH + chh];
    __syncthreads();

    for (int t = -1; t < cS; ++t) {
        const int p = t & 1;
        // prefetch L0's gin[t+1] (h-independent) at iteration start
        float pg0 = 0.f, pg1 = 0.f, pg2 = 0.f, pg3 = 0.f;
        if (t < cS - 1) {
            const float* gin = d_g0in + ((size_t)((t + 1) * 64 + cb)) * cG2;
            pg0 = ldg32(gin + 0 * cH + chh);
            pg1 = ldg32(gin + 1 * cH + chh);
            pg2 = ldg32(gin + 2 * cH + chh);
            pg3 = ldg32(gin + 3 * cH + chh);
        }
        unsigned long long acc[64];
        if (t >= 0) {  // L1(t): [h0new(t) | h1(t-1)], K=1024
#pragma unroll
            for (int i = 0; i < 64; i++) acc[i] = 0ull;
            if (ks < 8) mv(acc, d_h0B[p], w1, ks * 32, ks * 32 + 32, 0, bg);
            else        mv(acc, d_h1B[p], w1, (ks - 8) * 32, (ks - 8) * 32 + 32, 256, bg);
            red_store(red1, acc);
        }
        if (t < cS - 1) {  // L0(t+1): h0new(t), K=512
#pragma unroll
            for (int i = 0; i < 64; i++) acc[i] = 0ull;
            mv(acc, d_h0B[p], w0, ks * 16, ks * 16 + 16, 0, bg);
            red_store(red0, acc);
        }
        __syncthreads();

        if (t >= 0) {
            float gi = gsum(red1, 0 + chl, cb) + bias1[0];
            float gf = gsum(red1, 4 + chl, cb) + bias1[1];
            float gg = gsum(red1, 8 + chl, cb) + bias1[2];
            float go = gsum(red1, 12 + chl, cb) + bias1[3];
            c1 = sigm(gf) * c1 + sigm(gi) * tanhf(gg);
            float h1v = sigm(go) * tanhf(c1);
            d_h1B[p ^ 1][(chh >> 1) * 128 + cb * 2 + (chh & 1)] = h1v;
            d_outs[((size_t)(t * 64 + cb)) * cH + chh] = h1v;
        }
        if (t < cS - 1) {
            float gi = gsum(red0, 0 + chl, cb) + pg0;
            float gf = gsum(red0, 4 + chl, cb) + pg1;
            float gg = gsum(red0, 8 + chl, cb) + pg2;
            float go = gsum(red0, 12 + chl, cb) + pg3;
            c0 = sigm(gf) * c0 + sigm(gi) * tanhf(gg);
            float h0v = sigm(go) * tanhf(c0);
            d_h0B[p ^ 1][(chh >> 1) * 128 + cb * 2 + (chh & 1)] = h0v;
            gbar(2, 0, 128, (unsigned)(t + 2));
        }
    }
}

__global__ __launch_bounds__(32) void viterbi_kernel(
    const int* __restrict__ lengths, const float* __restrict__ trans, float* __restrict__ outp) {
    __shared__ float score_sm[cT];
    __shared__ uint8_t bp_sm[cS - 1][cT];
    const int b = blockIdx.x, i = threadIdx.x;
    const int len = lengths[b];
    float trow[cT];
    if (i < cT) {
#pragma unroll
        for (int j = 0; j < cT; j++) trow[j] = trans[i * cT + j];
        score_sm[i] = d_feats[(size_t)b * cT + i] + trow[START_TAG];
    }
    __syncwarp();
    for (int s = 1; s < cS; s++) {
        float ft = 0.f;
        if (i < cT) ft = d_feats[((size_t)s * cB + b) * cT + i];
        bool m = s < len;
        float best = -1e30f;
        int bj = 0;
        if (i < cT) {
#pragma unroll
            for (int j = 0; j < cT; j++) {
                float c = score_sm[j] + trow[j];
                if (c > best) { best = c; bj = j; }
            }
        }
        __syncwarp();
        if (i < cT) {
            if (m) score_sm[i] = best + ft;
            bp_sm[s - 1][i] = (uint8_t)(m ? bj : i);
        }
        __syncwarp();
    }
    if (i == 0) {
        float best = -1e30f;
        int bt = 0;
        for (int t = 0; t < cT; t++) {
            float v = score_sm[t] + trans[STOP_TAG * cT + t];
            if (v > best) { best = v; bt = t; }
        }
        outp[b] = best;
        int tag = bt;
        outp[cB + (size_t)b * cS + (cS - 1)] = (float)tag;
        for (int s = cS - 2; s >= 0; s--) {
            tag = bp_sm[s][tag];
            outp[cB + (size_t)b * cS + s] = (float)tag;
        }
    }
}

extern "C" void kernel_launch(void* const* d_in, const int* in_sizes, int n_in,
                              void* d_out, int out_size) {
    const int*   sentence = (const int*)  d_in[0];
    const int*   lengths  = (const int*)  d_in[1];
    const float* emb      = (const float*)d_in[2];
    const float* wih_f    = (const float*)d_in[3];
    const float* whh_f    = (const float*)d_in[4];
    const float* b_f      = (const float*)d_in[5];
    const float* wih_b    = (const float*)d_in[6];
    const float* whh_b    = (const float*)d_in[7];
    const float* b_b      = (const float*)d_in[8];
    const float* h1_0     = (const float*)d_in[9];
    const float* c1_0     = (const float*)d_in[10];
    const float* wih_s    = (const float*)d_in[11];
    const float* whh_s    = (const float*)d_in[12];
    const float* b_s      = (const float*)d_in[13];
    const float* h2_0     = (const float*)d_in[14];
    const float* c2_0     = (const float*)d_in[15];
    const float* W_tag    = (const float*)d_in[16];
    const float* b_tag    = (const float*)d_in[17];
    const float* trans    = (const float*)d_in[18];
    float* outp = (float*)d_out;

    const int smemBi = 128 * 17 * 8 + 8 * 16 * 64 * 4;
    const int smemSt = (256 * 17 + 512 * 17) * 8 + 2 * 8 * 16 * 64 * 4;
    static bool done = false;
    if (!done) {
        cudaFuncSetAttribute(bilstm_scan, cudaFuncAttributeMaxDynamicSharedMemorySize, smemBi);
        cudaFuncSetAttribute(stacked_scan, cudaFuncAttributeMaxDynamicSharedMemorySize, smemSt);
        done = true;
    }
    float *xbuf, *gxf, *gxb, *bibuf, *g0in, *outs, *feats;
    cudaGetSymbolAddress((void**)&xbuf, d_x);
    cudaGetSymbolAddress((void**)&gxf, d_gxf);
    cudaGetSymbolAddress((void**)&gxb, d_gxb);
    cudaGetSymbolAddress((void**)&bibuf, d_bi);
    cudaGetSymbolAddress((void**)&g0in, d_g0in);
    cudaGetSymbolAddress((void**)&outs, d_outs);
    cudaGetSymbolAddress((void**)&feats, d_feats);

    init_kernel<<<64, 256>>>(h1_0, h2_0);
    gather_kernel<<<cM, cE>>>(sentence, emb);
    dim3 g1(cG1 / 128, cM / 128);
    gemmT<<<g1, 256>>>(xbuf, wih_f, b_f, gxf, cM, cG1, cE);
    gemmT<<<g1, 256>>>(xbuf, wih_b, b_b, gxb, cM, cG1, cE);
    bilstm_scan<<<128, 256, smemBi>>>(whh_f, whh_b, c1_0, h1_0, lengths);
    dim3 g2(cG2 / 128, cM / 128);
    gemmT<<<g2, 256>>>(bibuf, wih_s, b_s, g0in, cM, cG2, cH);
    stacked_scan<<<128, 256, smemSt>>>(wih_s, whh_s, b_s, c2_0);
    dim3 g3(1, cM / 128);
    gemmT<<<g3, 256>>>(outs, W_tag, b_tag, feats, cM, cT, cH);
    viterbi_kernel<<<cB, 32>>>(lengths, trans, outp);
}